// round 7
// baseline (speedup 1.0000x reference)
#include <cuda_runtime.h>
#include <math.h>
#include <stdint.h>

// Problem constants (fixed by the dataset instance)
#define Bsz   16384
#define Csz   2048
#define Ksz   200
#define NCsz  1000
#define SLOTS 32

// GEMM1 tiling (v5: packed f32x2)
#define BM      32
#define BK      32
#define NP      224   // concept dim padded 200 -> 224 = 32*7
#define S2      36    // padded k-stride for sp
#define THREADS 256

// GEMM2 tiling (v4, unchanged)
#define TNO 128
#define RB  128

// ---------------- packed f32x2 helpers (Blackwell FFMA2 path) ----------------
__device__ __forceinline__ uint64_t ffma2(uint64_t a, uint64_t b, uint64_t c) {
    uint64_t d;
    asm("fma.rn.f32x2 %0, %1, %2, %3;" : "=l"(d) : "l"(a), "l"(b), "l"(c));
    return d;
}
__device__ __forceinline__ uint64_t fadd2(uint64_t a, uint64_t b) {
    uint64_t d;
    asm("add.rn.f32x2 %0, %1, %2;" : "=l"(d) : "l"(a), "l"(b));
    return d;
}
__device__ __forceinline__ uint64_t dup2(float v) {
    uint64_t d;
    asm("mov.b64 %0, {%1, %1};" : "=l"(d) : "f"(v));
    return d;
}
__device__ __forceinline__ void unpack2(uint64_t p, float& lo, float& hi) {
    asm("mov.b64 {%0, %1}, %2;" : "=f"(lo), "=f"(hi) : "l"(p));
}

// ---------------- device scratch (no allocations allowed) ----------------
__device__ float g_proto[Ksz * Csz];                    // normalized prototypes
__device__ __align__(16) float g_fcwT[Ksz * NCsz];      // fc_w transposed: [K][NC]
__device__ int   g_sidx[Bsz * SLOTS];                   // per-row surviving indices
__device__ float g_sval[Bsz * SLOTS];                   // per-row surviving LN'd values

// ---------------- normalize prototypes exactly like the reference ----------------
__global__ void k_norm_kernel(const float* __restrict__ concepts) {
    __shared__ float red[THREADS];
    __shared__ float nrm;
    int k = blockIdx.x;
    const float* row = concepts + (size_t)k * Csz;
    float s = 0.f;
    for (int c = threadIdx.x; c < Csz; c += THREADS) {
        float v = row[c];
        s = fmaf(v, v, s);
    }
    red[threadIdx.x] = s;
    __syncthreads();
    for (int off = THREADS / 2; off > 0; off >>= 1) {
        if (threadIdx.x < off) red[threadIdx.x] += red[threadIdx.x + off];
        __syncthreads();
    }
    if (threadIdx.x == 0) nrm = fmaxf(sqrtf(red[0]), 1e-12f);
    __syncthreads();
    float n = nrm;
    for (int c = threadIdx.x; c < Csz; c += THREADS)
        g_proto[(size_t)k * Csz + c] = row[c] / n;   // div.rn, matches F.normalize
}

// ---------------- tiled transpose fc_w [NC,K] -> [K,NC] ----------------
__global__ void k_tr_kernel(const float* __restrict__ fc_w) {
    __shared__ float tile[32][33];
    const int n0 = blockIdx.x * 32;
    const int k0 = blockIdx.y * 32;
    const int tx = threadIdx.x;
    const int ty = threadIdx.y;
    #pragma unroll
    for (int i = 0; i < 32; i += 8) {
        int n = n0 + ty + i, k = k0 + tx;
        tile[ty + i][tx] = (n < NCsz && k < Ksz) ? fc_w[(size_t)n * Ksz + k] : 0.f;
    }
    __syncthreads();
    #pragma unroll
    for (int i = 0; i < 32; i += 8) {
        int k = k0 + ty + i, n = n0 + tx;
        if (k < Ksz && n < NCsz)
            g_fcwT[(size_t)k * NCsz + n] = tile[tx][ty + i];
    }
}

// ---------------- fused GEMM1 (FFMA2) + LayerNorm + top-k select ----------------
// Each of the packed lanes runs the EXACT round-3 scalar chain (same kk order,
// same per-32-kk chunk merge) -> bit-identical feat values.
// Thread (tm = tid&7, tn = tid>>3): rows 4*tm + {0..3} (2 pairs), cols tn*7+j.
__global__ __launch_bounds__(THREADS, 2)
void k_main_kernel(const float* __restrict__ x,
                   const float* __restrict__ lnw,
                   const float* __restrict__ lnb,
                   const int*   __restrict__ dfi) {
    __shared__ float smem[BK * BM + NP * S2];  // 1024 + 8064 floats; feat[32][200] reuses it
    float* sxt = smem;                 // [BK][BM]  kk-major x tile (row fast)
    float* sp  = smem + BK * BM;       // [NP][S2]  concept tile (kk fast)

    const int tid = threadIdx.x;
    const int tm  = tid & 7;           // rows 4*tm .. 4*tm+3
    const int tn  = tid >> 3;          // cols tn*7 + j
    const int bm0 = blockIdx.x * BM;

    // zero the padding concept rows (n = 200..223) once
    for (int q = tid; q < (NP - Ksz) * S2; q += THREADS)
        sp[Ksz * S2 + q] = 0.f;

    uint64_t acc[2][7];                // [pair p][col j], lanes = rows 4tm+2p(+1)
    #pragma unroll
    for (int p = 0; p < 2; p++)
        #pragma unroll
        for (int j = 0; j < 7; j++) acc[p][j] = 0ull;

    const int lr  = tid & 31;          // x-loader row (0..31)
    const int lk4 = tid >> 5;          // x-loader k-chunk (0..7) -> kk = lk4*4..+3

    for (int k0 = 0; k0 < Csz; k0 += BK) {
        __syncthreads();
        // x tile: [32 rows][32 k] stored kk-major (transposed in smem)
        {
            float4 v = *reinterpret_cast<const float4*>(
                x + (size_t)(bm0 + lr) * Csz + k0 + lk4 * 4);
            sxt[(lk4 * 4 + 0) * BM + lr] = v.x;
            sxt[(lk4 * 4 + 1) * BM + lr] = v.y;
            sxt[(lk4 * 4 + 2) * BM + lr] = v.z;
            sxt[(lk4 * 4 + 3) * BM + lr] = v.w;
        }
        // concept tile: [200 rows][32 k], kk-fast layout (as round 3)
        for (int q = tid; q < Ksz * (BK / 4); q += THREADS) {
            int n  = q >> 3;
            int k4 = (q & 7) * 4;
            float4 v = *reinterpret_cast<const float4*>(
                g_proto + (size_t)n * Csz + k0 + k4);
            float* d = sp + n * S2 + k4;
            d[0] = v.x; d[1] = v.y; d[2] = v.z; d[3] = v.w;
        }
        __syncthreads();

        // chunked accumulation: fresh accT per 32-kk tile, merged after
        uint64_t accT[2][7];
        #pragma unroll
        for (int p = 0; p < 2; p++)
            #pragma unroll
            for (int j = 0; j < 7; j++) accT[p][j] = 0ull;

        #pragma unroll 8
        for (int kk = 0; kk < BK; kk++) {
            // b: scalar broadcast loads + duplicate into both packed lanes
            uint64_t bb[7];
            #pragma unroll
            for (int j = 0; j < 7; j++)
                bb[j] = dup2(sp[(tn * 7 + j) * S2 + kk]);
            // a: row-pairs, one aligned LDS.64 each (conflict-free)
            uint64_t a0 = *reinterpret_cast<const uint64_t*>(&sxt[kk * BM + 4 * tm]);
            uint64_t a1 = *reinterpret_cast<const uint64_t*>(&sxt[kk * BM + 4 * tm + 2]);
            #pragma unroll
            for (int j = 0; j < 7; j++) accT[0][j] = ffma2(a0, bb[j], accT[0][j]);
            #pragma unroll
            for (int j = 0; j < 7; j++) accT[1][j] = ffma2(a1, bb[j], accT[1][j]);
        }
        #pragma unroll
        for (int p = 0; p < 2; p++)
            #pragma unroll
            for (int j = 0; j < 7; j++) acc[p][j] = fadd2(acc[p][j], accT[p][j]);
    }
    __syncthreads();

    // ---- epilogue: store feat, LayerNorm (two-pass var), top-k, sparse emit ----
    const int lane = tid & 31;
    const int wid  = tid >> 5;
    const int fi   = *dfi;
    const int ktop = Ksz - fi;         // = 20

    float* feat = smem;                // [32][Ksz]

    #pragma unroll
    for (int p = 0; p < 2; p++) {
        #pragma unroll
        for (int j = 0; j < 7; j++) {
            int n = tn * 7 + j;
            if (n < Ksz) {
                float lo, hi;
                unpack2(acc[p][j], lo, hi);
                feat[(4 * tm + 2 * p + 0) * Ksz + n] = lo;
                feat[(4 * tm + 2 * p + 1) * Ksz + n] = hi;
            }
        }
    }
    __syncthreads();

    // one warp handles 4 rows (identical math to round 3)
    for (int rr = 0; rr < 4; rr++) {
        int rloc = wid * 4 + rr;
        int row  = bm0 + rloc;
        float f[7];
        float s1 = 0.f;
        #pragma unroll
        for (int j = 0; j < 7; j++) {
            int n = lane + 32 * j;
            float v = (n < Ksz) ? feat[rloc * Ksz + n] : 0.f;
            f[j] = v;
            s1 += v;
        }
        #pragma unroll
        for (int off = 16; off > 0; off >>= 1)
            s1 += __shfl_xor_sync(0xffffffffu, s1, off);
        float mu = s1 / (float)Ksz;
        float s2 = 0.f;
        #pragma unroll
        for (int j = 0; j < 7; j++) {
            int n = lane + 32 * j;
            if (n < Ksz) {
                float d = f[j] - mu;
                s2 = fmaf(d, d, s2);
            }
        }
        #pragma unroll
        for (int off = 16; off > 0; off >>= 1)
            s2 += __shfl_xor_sync(0xffffffffu, s2, off);
        float var  = s2 / (float)Ksz;
        float rstd = 1.f / sqrtf(var + 1e-5f);

        float v[7], av[7], sel[7];
        #pragma unroll
        for (int j = 0; j < 7; j++) {
            int n = lane + 32 * j;
            if (n < Ksz) {
                float z = (f[j] - mu) * rstd * lnw[n] + lnb[n];
                v[j] = z; av[j] = fabsf(z); sel[j] = av[j];
            } else { v[j] = 0.f; av[j] = -1.f; sel[j] = -1.f; }
        }
        float t = 0.f;
        for (int it = 0; it < ktop; it++) {
            float lm = sel[0]; int lj = 0;
            #pragma unroll
            for (int j = 1; j < 7; j++) if (sel[j] > lm) { lm = sel[j]; lj = j; }
            float m = lm;
            #pragma unroll
            for (int off = 16; off > 0; off >>= 1)
                m = fmaxf(m, __shfl_xor_sync(0xffffffffu, m, off));
            unsigned ball = __ballot_sync(0xffffffffu, lm == m);
            int leader = __ffs((int)ball) - 1;
            if (lane == leader) sel[lj] = -2.f;
            t = m;
        }
        int cnt = 0;
        #pragma unroll
        for (int j = 0; j < 7; j++) {
            bool pred = (av[j] - t > 0.f);
            unsigned msk = __ballot_sync(0xffffffffu, pred);
            if (pred) {
                int pos = cnt + __popc(msk & ((1u << lane) - 1u));
                g_sidx[(size_t)row * SLOTS + pos] = lane + 32 * j;
                g_sval[(size_t)row * SLOTS + pos] = v[j];
            }
            cnt += __popc(msk);
        }
        if (lane == 0) {
            for (int pd = cnt; pd < ktop; pd++) {
                g_sidx[(size_t)row * SLOTS + pd] = 0;
                g_sval[(size_t)row * SLOTS + pd] = 0.f;
            }
        }
    }
}

// ---------------- sparse GEMM2 v4 (unchanged from round 6) ----------------
__global__ __launch_bounds__(256, 2)
void k_out_kernel(const float* __restrict__ fcb,
                  const int*   __restrict__ dfi,
                  float* __restrict__ out) {
    extern __shared__ float4 ws4[];                 // [Ksz][32] float4 = 100KB
    float2* pk = (float2*)(ws4 + Ksz * 32);         // [32][SLOTS] packed (val, idx)

    const int tid  = threadIdx.x;
    const int lane = tid & 31;
    const int wid  = tid >> 5;
    const int cb   = blockIdx.y;
    const int col0 = cb * TNO + lane * 4;
    const bool vall = (col0 + 3) < NCsz;

    for (int q = tid; q < Ksz * 32; q += 256) {
        int k = q >> 5, t4 = q & 31;
        int c = cb * TNO + t4 * 4;
        float4 w;
        if (c + 3 < NCsz) {
            w = *reinterpret_cast<const float4*>(&g_fcwT[(size_t)k * NCsz + c]);
        } else {
            w.x = (c + 0 < NCsz) ? g_fcwT[(size_t)k * NCsz + c + 0] : 0.f;
            w.y = (c + 1 < NCsz) ? g_fcwT[(size_t)k * NCsz + c + 1] : 0.f;
            w.z = (c + 2 < NCsz) ? g_fcwT[(size_t)k * NCsz + c + 2] : 0.f;
            w.w = 0.f;
        }
        ws4[q] = w;
    }

    float4 bb;
    bb.x = (col0 + 0 < NCsz) ? fcb[col0 + 0] : 0.f;
    bb.y = (col0 + 1 < NCsz) ? fcb[col0 + 1] : 0.f;
    bb.z = (col0 + 2 < NCsz) ? fcb[col0 + 2] : 0.f;
    bb.w = (col0 + 3 < NCsz) ? fcb[col0 + 3] : 0.f;
    const int ktop = Ksz - *dfi;
    const int r0   = blockIdx.x * RB;

    for (int batch = 0; batch < RB; batch += 32) {
        __syncthreads();
        for (int q = tid; q < 32 * ktop; q += 256) {
            int r = q / ktop, j = q - r * ktop;
            size_t g = (size_t)(r0 + batch + r) * SLOTS + j;
            pk[r * SLOTS + j] = make_float2(g_sval[g], __int_as_float(g_sidx[g]));
        }
        __syncthreads();

        float4 acc[4];
        #pragma unroll
        for (int r = 0; r < 4; r++) acc[r] = make_float4(0.f, 0.f, 0.f, 0.f);
        const float2* pkr = pk + (wid * 4) * SLOTS;
        #pragma unroll 5
        for (int j = 0; j < ktop; j++) {
            #pragma unroll
            for (int r = 0; r < 4; r++) {
                float2 p = pkr[r * SLOTS + j];
                int idx  = __float_as_int(p.y);
                float4 w = ws4[idx * 32 + lane];
                acc[r].x = fmaf(p.x, w.x, acc[r].x);
                acc[r].y = fmaf(p.x, w.y, acc[r].y);
                acc[r].z = fmaf(p.x, w.z, acc[r].z);
                acc[r].w = fmaf(p.x, w.w, acc[r].w);
            }
        }
        #pragma unroll
        for (int r = 0; r < 4; r++) {
            size_t row = (size_t)(r0 + batch + wid * 4 + r);
            if (vall) {
                float4 o = make_float4(acc[r].x + bb.x, acc[r].y + bb.y,
                                       acc[r].z + bb.z, acc[r].w + bb.w);
                *reinterpret_cast<float4*>(&out[row * NCsz + col0]) = o;
            } else {
                if (col0 + 0 < NCsz) out[row * NCsz + col0 + 0] = acc[r].x + bb.x;
                if (col0 + 1 < NCsz) out[row * NCsz + col0 + 1] = acc[r].y + bb.y;
                if (col0 + 2 < NCsz) out[row * NCsz + col0 + 2] = acc[r].z + bb.z;
            }
        }
    }
}

// ---------------- launch ----------------
extern "C" void kernel_launch(void* const* d_in, const int* in_sizes, int n_in,
                              void* d_out, int out_size) {
    const float* x        = (const float*)d_in[0];
    const float* concepts = (const float*)d_in[1];
    const float* lnw      = (const float*)d_in[2];
    const float* lnb      = (const float*)d_in[3];
    const float* fcw      = (const float*)d_in[4];
    const float* fcb      = (const float*)d_in[5];
    const int*   dfi      = (const int*)d_in[6];
    float* out = (float*)d_out;

    const int smem2 = Ksz * 32 * (int)sizeof(float4)
                    + 32 * SLOTS * (int)sizeof(float2);   // 100KB + 8KB
    cudaFuncSetAttribute(k_out_kernel,
                         cudaFuncAttributeMaxDynamicSharedMemorySize, smem2);

    k_norm_kernel<<<Ksz, THREADS>>>(concepts);
    dim3 trg((NCsz + 31) / 32, (Ksz + 31) / 32);
    k_tr_kernel<<<trg, dim3(32, 8)>>>(fcw);
    k_main_kernel<<<Bsz / BM, THREADS>>>(x, lnw, lnb, dfi);
    dim3 g2(Bsz / RB, (NCsz + TNO - 1) / TNO);
    k_out_kernel<<<g2, 256, smem2>>>(fcb, dfi, out);
}